// round 5
// baseline (speedup 1.0000x reference)
#include <cuda_runtime.h>
#include <cstdint>
#include <cstddef>

// ---------------- problem constants ----------------
#define FANOUT 10
#define N0_SZ 1362944
#define N1_SZ 123904
#define N2_SZ 11264
#define SEEDS_SZ 1024
#define IN_DIM 256
#define H_DIM 512
#define C_DIM 256

// ---------------- device scratch (allocation-free rule) ----------------
__device__ __align__(16) float g_xr[(size_t)N1_SZ * IN_DIM];
__device__ __align__(16) float g_neigh0[(size_t)N1_SZ * IN_DIM];
__device__ __align__(16) float g_h1[(size_t)N1_SZ * H_DIM];
__device__ __align__(16) float g_neigh1[(size_t)N2_SZ * H_DIM];
__device__ __align__(16) float g_h2[(size_t)N2_SZ * H_DIM];
__device__ __align__(16) float g_neigh2[(size_t)SEEDS_SZ * H_DIM];
__device__ __align__(16) float g_Wt0s[(size_t)H_DIM * IN_DIM];
__device__ __align__(16) float g_Wt0n[(size_t)H_DIM * IN_DIM];
__device__ __align__(16) float g_Wt1s[(size_t)H_DIM * H_DIM];
__device__ __align__(16) float g_Wt1n[(size_t)H_DIM * H_DIM];
__device__ __align__(16) float g_Wt2s[(size_t)C_DIM * H_DIM];
__device__ __align__(16) float g_Wt2n[(size_t)C_DIM * H_DIM];

// ---------------- helpers (portable sm_80+ PTX) ----------------
__device__ __forceinline__ uint32_t smem_u32(const void* p) {
    uint32_t a;
    asm("{ .reg .u64 t; cvta.to.shared.u64 t, %1; cvt.u32.u64 %0, t; }" : "=r"(a) : "l"(p));
    return a;
}
__device__ __forceinline__ float cvt_tf32(float x) {
    float r; asm("cvt.rna.tf32.f32 %0, %1;" : "=f"(r) : "f"(x)); return r;
}
__device__ __forceinline__ void cp_async16(uint32_t dst, const void* src) {
    asm volatile("cp.async.cg.shared.global [%0], [%1], 16;" :: "r"(dst), "l"(src));
}
#define CP_COMMIT() asm volatile("cp.async.commit_group;" ::: "memory")
#define CP_WAIT(n)  asm volatile("cp.async.wait_group %0;" :: "n"(n) : "memory")

__device__ __forceinline__ void mma_tf32(float c[4],
                                         uint32_t a0, uint32_t a1, uint32_t a2, uint32_t a3,
                                         uint32_t b0, uint32_t b1) {
    asm volatile(
        "mma.sync.aligned.m16n8k8.row.col.f32.tf32.tf32.f32 "
        "{%0,%1,%2,%3}, {%4,%5,%6,%7}, {%8,%9}, {%0,%1,%2,%3};"
        : "+f"(c[0]), "+f"(c[1]), "+f"(c[2]), "+f"(c[3])
        : "r"(a0), "r"(a1), "r"(a2), "r"(a3), "r"(b0), "r"(b1));
}

__host__ __device__ __forceinline__ int perm8(int i) { return (i & 3) * 2 + (i >> 2); }

// ---------------------------------------------------------------------------
// gather-mean (PERM=true: raw input, permuted output; false: layout-preserving)
// ---------------------------------------------------------------------------
template <bool PERM>
__global__ void gather_mean_kernel(const float* __restrict__ h,
                                   const int* __restrict__ src,
                                   float* __restrict__ out, int dim8, int num_dst) {
    const int d = blockIdx.x * blockDim.y + threadIdx.y;
    if (d >= num_dst) return;
    const int t = threadIdx.x;
    const int* s = src + (size_t)d * FANOUT;
    const float4* h4 = (const float4*)h;

    float4 a0 = make_float4(0.f, 0.f, 0.f, 0.f);
    float4 a1 = make_float4(0.f, 0.f, 0.f, 0.f);
#pragma unroll
    for (int e = 0; e < FANOUT; ++e) {
        int r = __ldg(s + e);
        const float4* p = h4 + ((size_t)r * dim8 + t) * 2;
        float4 v0 = __ldg(p), v1 = __ldg(p + 1);
        a0.x += v0.x; a0.y += v0.y; a0.z += v0.z; a0.w += v0.w;
        a1.x += v1.x; a1.y += v1.y; a1.z += v1.z; a1.w += v1.w;
    }
    const float inv = 1.0f / FANOUT;
    a0.x = cvt_tf32(a0.x * inv); a0.y = cvt_tf32(a0.y * inv);
    a0.z = cvt_tf32(a0.z * inv); a0.w = cvt_tf32(a0.w * inv);
    a1.x = cvt_tf32(a1.x * inv); a1.y = cvt_tf32(a1.y * inv);
    a1.z = cvt_tf32(a1.z * inv); a1.w = cvt_tf32(a1.w * inv);

    float4* o = (float4*)out + ((size_t)d * dim8 + t) * 2;
    if (PERM) {
        o[0] = make_float4(a0.x, a1.x, a0.y, a1.y);
        o[1] = make_float4(a0.z, a1.z, a0.w, a1.w);
    } else {
        o[0] = a0;
        o[1] = a1;
    }
}

// ---------------------------------------------------------------------------
// round+permute copy (with element offset so it can be split across launches)
// ---------------------------------------------------------------------------
__global__ void round_perm_kernel(const float* __restrict__ src,
                                  float* __restrict__ dst, size_t base8, size_t n8) {
    size_t id = base8 + (size_t)blockIdx.x * blockDim.x + threadIdx.x;
    if (id >= n8) return;
    const float4* p = (const float4*)src + id * 2;
    float4 v0 = __ldg(p), v1 = __ldg(p + 1);
    v0.x = cvt_tf32(v0.x); v0.y = cvt_tf32(v0.y); v0.z = cvt_tf32(v0.z); v0.w = cvt_tf32(v0.w);
    v1.x = cvt_tf32(v1.x); v1.y = cvt_tf32(v1.y); v1.z = cvt_tf32(v1.z); v1.w = cvt_tf32(v1.w);
    float4* o = (float4*)dst + id * 2;
    o[0] = make_float4(v0.x, v1.x, v0.y, v1.y);
    o[1] = make_float4(v0.z, v1.z, v0.w, v1.w);
}

// ---------------------------------------------------------------------------
// W[K,N] -> Wt[N, perm(K)] with tf32 rounding. grid(N/32, K/32), block(32,8)
// ---------------------------------------------------------------------------
__global__ void transpose_tf32_kernel(const float* __restrict__ W,
                                      float* __restrict__ Wt, int K, int N) {
    __shared__ float t[32][33];
    int bx = blockIdx.x * 32, by = blockIdx.y * 32;
#pragma unroll
    for (int i = threadIdx.y; i < 32; i += 8)
        t[i][threadIdx.x] = __ldg(W + (size_t)(by + i) * N + bx + threadIdx.x);
    __syncthreads();
#pragma unroll
    for (int i = threadIdx.y; i < 32; i += 8) {
        int k = by + threadIdx.x;
        int kp = (k & ~7) | perm8(k & 7);
        Wt[(size_t)(bx + i) * K + kp] = cvt_tf32(t[threadIdx.x][i]);
    }
}

// ---------------------------------------------------------------------------
// tf32 mma.sync dual-GEMM, 3-stage cp.async pipeline, BK=16.
// A0,A1: [M,K] tf32-rounded k-permuted; B0t,B1t: [N,K] likewise.
// BM=128, BN template (128 or 64), 8 warps 2m x (4n), warp tile 64 x BN/4.
// ---------------------------------------------------------------------------
#define BK 16
#define PADK 24
#define A_TILE_F (128 * PADK)

template <int BN, bool INTERMEDIATE>
__global__ __launch_bounds__(256, 2)
void sage_mma_gemm(const float* __restrict__ A0, const float* __restrict__ A1,
                   const float* __restrict__ B0t, const float* __restrict__ B1t,
                   const float* __restrict__ bias, float* __restrict__ C,
                   int K, int N) {
    constexpr int B_TILE_F = BN * PADK;
    constexpr int STAGE_F = A_TILE_F + B_TILE_F;
    constexpr int NI = BN / 32;                 // per-warp n-fragments
    extern __shared__ float sm[];
    const uint32_t sbase = smem_u32(sm);
    const int tid = threadIdx.x, lane = tid & 31, w = tid >> 5;
    const int wm = w >> 2, wn = w & 3;
    const int m0 = blockIdx.y * 128, n0 = blockIdx.x * BN;
    const int kc = K / BK;
    const int T = 2 * kc;

    float acc[4][NI][4];
#pragma unroll
    for (int mi = 0; mi < 4; ++mi)
#pragma unroll
        for (int ni = 0; ni < NI; ++ni)
#pragma unroll
            for (int r = 0; r < 4; ++r) acc[mi][ni][r] = 0.f;

    auto stage = [&](int chunk, int s) {
        const int pair = (chunk >= kc) ? 1 : 0;
        const int k0 = (pair ? chunk - kc : chunk) * BK;
        const float* A = pair ? A1 : A0;
        const float* B = pair ? B1t : B0t;
        const uint32_t da = sbase + (uint32_t)(s * STAGE_F) * 4;
        const uint32_t db = da + (uint32_t)A_TILE_F * 4;
        // A: 128 rows x 16 floats = 512 cp16
#pragma unroll
        for (int i = tid; i < 512; i += 256) {
            int row = i >> 2, c4 = i & 3;
            cp_async16(da + (uint32_t)(row * PADK + c4 * 4) * 4,
                       A + (size_t)(m0 + row) * K + k0 + c4 * 4);
        }
        // B: BN rows x 16 floats
#pragma unroll
        for (int i = tid; i < BN * 4; i += 256) {
            int row = i >> 2, c4 = i & 3;
            cp_async16(db + (uint32_t)(row * PADK + c4 * 4) * 4,
                       B + (size_t)(n0 + row) * K + k0 + c4 * 4);
        }
        CP_COMMIT();
    };

    stage(0, 0);
    if (1 < T) stage(1, 1);

    const int q2 = (lane & 3) * 2;
    const int rr = lane >> 2;

    for (int c = 0; c < T; ++c) {
        if (c + 2 < T) { stage(c + 2, (c + 2) % 3); CP_WAIT(2); }
        else if (c + 1 < T) { CP_WAIT(1); }
        else { CP_WAIT(0); }
        __syncthreads();

        const float* As = sm + (c % 3) * STAGE_F;
        const float* Bs = As + A_TILE_F;
#pragma unroll
        for (int ks = 0; ks < 2; ++ks) {
            uint32_t a[4][4], b[NI][2];
            const int cc = ks * 8 + q2;
#pragma unroll
            for (int mi = 0; mi < 4; ++mi) {
                const float* p = As + (wm * 64 + mi * 16 + rr) * PADK + cc;
                float2 lo = *(const float2*)p;
                float2 hi = *(const float2*)(p + 8 * PADK);
                a[mi][0] = __float_as_uint(lo.x);
                a[mi][1] = __float_as_uint(hi.x);
                a[mi][2] = __float_as_uint(lo.y);
                a[mi][3] = __float_as_uint(hi.y);
            }
#pragma unroll
            for (int ni = 0; ni < NI; ++ni) {
                const float* p = Bs + (wn * (BN / 4) + ni * 8 + rr) * PADK + cc;
                float2 v = *(const float2*)p;
                b[ni][0] = __float_as_uint(v.x);
                b[ni][1] = __float_as_uint(v.y);
            }
#pragma unroll
            for (int mi = 0; mi < 4; ++mi)
#pragma unroll
                for (int ni = 0; ni < NI; ++ni)
                    mma_tf32(acc[mi][ni], a[mi][0], a[mi][1], a[mi][2], a[mi][3],
                             b[ni][0], b[ni][1]);
        }
        __syncthreads();
    }

    // epilogue
#pragma unroll
    for (int ni = 0; ni < NI; ++ni) {
        const int n = n0 + wn * (BN / 4) + ni * 8 + 2 * (lane & 3);
        const float bx = __ldg(bias + n), by = __ldg(bias + n + 1);
#pragma unroll
        for (int mi = 0; mi < 4; ++mi) {
            const int m = m0 + wm * 64 + mi * 16 + (lane >> 2);
            float v00 = acc[mi][ni][0] + bx, v01 = acc[mi][ni][1] + by;
            float v10 = acc[mi][ni][2] + bx, v11 = acc[mi][ni][3] + by;
            if (INTERMEDIATE) {
                v00 = cvt_tf32(fmaxf(v00, 0.f)); v01 = cvt_tf32(fmaxf(v01, 0.f));
                v10 = cvt_tf32(fmaxf(v10, 0.f)); v11 = cvt_tf32(fmaxf(v11, 0.f));
                const int g = n & ~7;
                const int p0 = g | perm8(n & 7), p1 = g | perm8((n + 1) & 7);
                C[(size_t)m * N + p0] = v00;
                C[(size_t)m * N + p1] = v01;
                C[(size_t)(m + 8) * N + p0] = v10;
                C[(size_t)(m + 8) * N + p1] = v11;
            } else {
                *(float2*)(C + (size_t)m * N + n) = make_float2(v00, v01);
                *(float2*)(C + (size_t)(m + 8) * N + n) = make_float2(v10, v11);
            }
        }
    }
}

#define SMEM_BN128 (3 * (A_TILE_F + 128 * PADK) * 4)
#define SMEM_BN64  (3 * (A_TILE_F + 64 * PADK) * 4)

// ---------------------------------------------------------------------------
extern "C" void kernel_launch(void* const* d_in, const int* in_sizes, int n_in,
                              void* d_out, int out_size) {
    const float* x   = (const float*)d_in[0];
    const float* Ws0 = (const float*)d_in[1];
    const float* Wn0 = (const float*)d_in[2];
    const float* b0  = (const float*)d_in[3];
    const float* Ws1 = (const float*)d_in[4];
    const float* Wn1 = (const float*)d_in[5];
    const float* b1  = (const float*)d_in[6];
    const float* Ws2 = (const float*)d_in[7];
    const float* Wn2 = (const float*)d_in[8];
    const float* b2  = (const float*)d_in[9];
    const int*   e0  = (const int*)d_in[10];
    const int*   e1  = (const int*)d_in[11];
    const int*   e2  = (const int*)d_in[12];
    float* out = (float*)d_out;

    float *xr, *neigh0, *h1, *neigh1, *h2, *neigh2;
    float *Wt0s, *Wt0n, *Wt1s, *Wt1n, *Wt2s, *Wt2n;
    cudaGetSymbolAddress((void**)&xr,     g_xr);
    cudaGetSymbolAddress((void**)&neigh0, g_neigh0);
    cudaGetSymbolAddress((void**)&h1,     g_h1);
    cudaGetSymbolAddress((void**)&neigh1, g_neigh1);
    cudaGetSymbolAddress((void**)&h2,     g_h2);
    cudaGetSymbolAddress((void**)&neigh2, g_neigh2);
    cudaGetSymbolAddress((void**)&Wt0s,   g_Wt0s);
    cudaGetSymbolAddress((void**)&Wt0n,   g_Wt0n);
    cudaGetSymbolAddress((void**)&Wt1s,   g_Wt1s);
    cudaGetSymbolAddress((void**)&Wt1n,   g_Wt1n);
    cudaGetSymbolAddress((void**)&Wt2s,   g_Wt2s);
    cudaGetSymbolAddress((void**)&Wt2n,   g_Wt2n);

    cudaFuncSetAttribute((const void*)sage_mma_gemm<128, true>,
                         cudaFuncAttributeMaxDynamicSharedMemorySize, SMEM_BN128);
    cudaFuncSetAttribute((const void*)sage_mma_gemm<64, true>,
                         cudaFuncAttributeMaxDynamicSharedMemorySize, SMEM_BN64);
    cudaFuncSetAttribute((const void*)sage_mma_gemm<64, false>,
                         cudaFuncAttributeMaxDynamicSharedMemorySize, SMEM_BN64);

    const size_t n8 = (size_t)N1_SZ * IN_DIM / 8;   // 3964928
    const size_t half8 = n8 / 2;

    // #1: gather0
    gather_mean_kernel<true><<<N1_SZ / 8, dim3(IN_DIM / 8, 8)>>>(x, e0, neigh0, IN_DIM / 8, N1_SZ);
    // #2-#3: rounded+permuted copy of x[:N1] (two halves)
    round_perm_kernel<<<(unsigned)((half8 + 255) / 256), 256>>>(x, xr, 0, half8);
    round_perm_kernel<<<(unsigned)((n8 - half8 + 255) / 256), 256>>>(x, xr, half8, n8);
    // #4-#9: weight transposes
    transpose_tf32_kernel<<<dim3(H_DIM / 32, IN_DIM / 32), dim3(32, 8)>>>(Ws0, Wt0s, IN_DIM, H_DIM);
    transpose_tf32_kernel<<<dim3(H_DIM / 32, IN_DIM / 32), dim3(32, 8)>>>(Wn0, Wt0n, IN_DIM, H_DIM);
    transpose_tf32_kernel<<<dim3(H_DIM / 32, H_DIM / 32), dim3(32, 8)>>>(Ws1, Wt1s, H_DIM, H_DIM);
    transpose_tf32_kernel<<<dim3(H_DIM / 32, H_DIM / 32), dim3(32, 8)>>>(Wn1, Wt1n, H_DIM, H_DIM);
    transpose_tf32_kernel<<<dim3(C_DIM / 32, H_DIM / 32), dim3(32, 8)>>>(Ws2, Wt2s, H_DIM, C_DIM);
    transpose_tf32_kernel<<<dim3(C_DIM / 32, H_DIM / 32), dim3(32, 8)>>>(Wn2, Wt2n, H_DIM, C_DIM);
    // #10: Layer-0 dual GEMM (profiled slot)
    sage_mma_gemm<128, true><<<dim3(H_DIM / 128, N1_SZ / 128), 256, SMEM_BN128>>>(
        xr, neigh0, Wt0s, Wt0n, b0, h1, IN_DIM, H_DIM);
    // #11: gather1
    gather_mean_kernel<false><<<N2_SZ / 4, dim3(H_DIM / 8, 4)>>>(h1, e1, neigh1, H_DIM / 8, N2_SZ);
    // #12: Layer-1 dual GEMM (BN=64 for tail utilization: 704 CTAs)
    sage_mma_gemm<64, true><<<dim3(H_DIM / 64, N2_SZ / 128), 256, SMEM_BN64>>>(
        h1, neigh1, Wt1s, Wt1n, b1, h2, H_DIM, H_DIM);
    // #13: gather2
    gather_mean_kernel<false><<<SEEDS_SZ / 4, dim3(H_DIM / 8, 4)>>>(h2, e2, neigh2, H_DIM / 8, SEEDS_SZ);
    // #14: Layer-2 dual GEMM
    sage_mma_gemm<64, false><<<dim3(C_DIM / 64, SEEDS_SZ / 128), 256, SMEM_BN64>>>(
        h2, neigh2, Wt2s, Wt2n, b2, out, H_DIM, C_DIM);
}

// round 6
// speedup vs baseline: 1.0115x; 1.0115x over previous
#include <cuda_runtime.h>
#include <cstdint>
#include <cstddef>

// ---------------- problem constants ----------------
#define FANOUT 10
#define N0_SZ 1362944
#define N1_SZ 123904
#define N2_SZ 11264
#define SEEDS_SZ 1024
#define IN_DIM 256
#define H_DIM 512
#define C_DIM 256

// ---------------- device scratch (allocation-free rule) ----------------
__device__ __align__(16) float g_neigh0[(size_t)N1_SZ * IN_DIM];
__device__ __align__(16) float g_h1[(size_t)N1_SZ * H_DIM];
__device__ __align__(16) float g_neigh1[(size_t)N2_SZ * H_DIM];
__device__ __align__(16) float g_h2[(size_t)N2_SZ * H_DIM];
__device__ __align__(16) float g_neigh2[(size_t)SEEDS_SZ * H_DIM];
// transposed + tf32-rounded + k-permuted weights: Wt[n][perm(k)] = tf32(W[k][n])
__device__ __align__(16) float g_Wt0s[(size_t)H_DIM * IN_DIM];
__device__ __align__(16) float g_Wt0n[(size_t)H_DIM * IN_DIM];
__device__ __align__(16) float g_Wt1s[(size_t)H_DIM * H_DIM];
__device__ __align__(16) float g_Wt1n[(size_t)H_DIM * H_DIM];
__device__ __align__(16) float g_Wt2s[(size_t)C_DIM * H_DIM];
__device__ __align__(16) float g_Wt2n[(size_t)C_DIM * H_DIM];

// ---------------- helpers (portable sm_80+ PTX) ----------------
__device__ __forceinline__ uint32_t smem_u32(const void* p) {
    uint32_t a;
    asm("{ .reg .u64 t; cvta.to.shared.u64 t, %1; cvt.u32.u64 %0, t; }" : "=r"(a) : "l"(p));
    return a;
}
__device__ __forceinline__ float cvt_tf32(float x) {
    float r; asm("cvt.rna.tf32.f32 %0, %1;" : "=f"(r) : "f"(x)); return r;
}
__device__ __forceinline__ uint32_t f2tf(float x) { return __float_as_uint(cvt_tf32(x)); }
__device__ __forceinline__ void cp_async16(uint32_t dst, const void* src) {
    asm volatile("cp.async.cg.shared.global [%0], [%1], 16;" :: "r"(dst), "l"(src));
}
#define CP_COMMIT() asm volatile("cp.async.commit_group;" ::: "memory")
#define CP_WAIT(n)  asm volatile("cp.async.wait_group %0;" :: "n"(n) : "memory")

__device__ __forceinline__ void mma_tf32(float c[4],
                                         uint32_t a0, uint32_t a1, uint32_t a2, uint32_t a3,
                                         uint32_t b0, uint32_t b1) {
    asm volatile(
        "mma.sync.aligned.m16n8k8.row.col.f32.tf32.tf32.f32 "
        "{%0,%1,%2,%3}, {%4,%5,%6,%7}, {%8,%9}, {%0,%1,%2,%3};"
        : "+f"(c[0]), "+f"(c[1]), "+f"(c[2]), "+f"(c[3])
        : "r"(a0), "r"(a1), "r"(a2), "r"(a3), "r"(b0), "r"(b1));
}

__host__ __device__ __forceinline__ int perm8(int i) { return (i & 3) * 2 + (i >> 2); }

// ---------------------------------------------------------------------------
// gather-mean (PERM=true: raw input, permuted+rounded output; false: layout-
// preserving — input already permuted/rounded)
// ---------------------------------------------------------------------------
template <bool PERM>
__global__ void gather_mean_kernel(const float* __restrict__ h,
                                   const int* __restrict__ src,
                                   float* __restrict__ out, int dim8, int num_dst) {
    const int d = blockIdx.x * blockDim.y + threadIdx.y;
    if (d >= num_dst) return;
    const int t = threadIdx.x;
    const int* s = src + (size_t)d * FANOUT;
    const float4* h4 = (const float4*)h;

    float4 a0 = make_float4(0.f, 0.f, 0.f, 0.f);
    float4 a1 = make_float4(0.f, 0.f, 0.f, 0.f);
#pragma unroll
    for (int e = 0; e < FANOUT; ++e) {
        int r = __ldg(s + e);
        const float4* p = h4 + ((size_t)r * dim8 + t) * 2;
        float4 v0 = __ldg(p), v1 = __ldg(p + 1);
        a0.x += v0.x; a0.y += v0.y; a0.z += v0.z; a0.w += v0.w;
        a1.x += v1.x; a1.y += v1.y; a1.z += v1.z; a1.w += v1.w;
    }
    const float inv = 1.0f / FANOUT;
    a0.x = cvt_tf32(a0.x * inv); a0.y = cvt_tf32(a0.y * inv);
    a0.z = cvt_tf32(a0.z * inv); a0.w = cvt_tf32(a0.w * inv);
    a1.x = cvt_tf32(a1.x * inv); a1.y = cvt_tf32(a1.y * inv);
    a1.z = cvt_tf32(a1.z * inv); a1.w = cvt_tf32(a1.w * inv);

    float4* o = (float4*)out + ((size_t)d * dim8 + t) * 2;
    if (PERM) {
        o[0] = make_float4(a0.x, a1.x, a0.y, a1.y);
        o[1] = make_float4(a0.z, a1.z, a0.w, a1.w);
    } else {
        o[0] = a0;
        o[1] = a1;
    }
}

// ---------------------------------------------------------------------------
// Merged weight transpose: all 6 W[K,N] -> Wt[N, perm(K)] in ONE launch.
// 32x32 tiles; block (32,8); 1024 total blocks.
// ---------------------------------------------------------------------------
struct TransposeJob { const float* W; float* Wt; int K; int N; int tile_base; };

__global__ void transpose_all_kernel(const float* W0, float* D0,
                                     const float* W1, float* D1,
                                     const float* W2, float* D2,
                                     const float* W3, float* D3,
                                     const float* W4, float* D4,
                                     const float* W5, float* D5) {
    // tile ranges: [0,128) Ws0, [128,256) Wn0, [256,512) Ws1,
    //              [512,768) Wn1, [768,896) Ws2, [896,1024) Wn2
    const int b = blockIdx.x;
    const float* W; float* Wt; int K, N, t;
    if (b < 256) {
        K = IN_DIM; N = H_DIM;
        if (b < 128) { W = W0; Wt = D0; t = b; }
        else         { W = W1; Wt = D1; t = b - 128; }
    } else if (b < 768) {
        K = H_DIM; N = H_DIM;
        if (b < 512) { W = W2; Wt = D2; t = b - 256; }
        else         { W = W3; Wt = D3; t = b - 512; }
    } else {
        K = H_DIM; N = C_DIM;
        if (b < 896) { W = W4; Wt = D4; t = b - 768; }
        else         { W = W5; Wt = D5; t = b - 896; }
    }
    const int ntx = N / 32;
    const int bx = (t % ntx) * 32, by = (t / ntx) * 32;

    __shared__ float tile[32][33];
#pragma unroll
    for (int i = threadIdx.y; i < 32; i += 8)
        tile[i][threadIdx.x] = __ldg(W + (size_t)(by + i) * N + bx + threadIdx.x);
    __syncthreads();
#pragma unroll
    for (int i = threadIdx.y; i < 32; i += 8) {
        int k = by + threadIdx.x;
        int kp = (k & ~7) | perm8(k & 7);
        Wt[(size_t)(bx + i) * K + kp] = cvt_tf32(tile[threadIdx.x][i]);
    }
}

// ---------------------------------------------------------------------------
// tf32 mma.sync dual-GEMM (R3 config: BK=32, PADK=40, double-buffered).
// A0RAW=true: A0 is raw fp32, unpermuted (cvt applied at fragment load).
// Otherwise A0 is tf32-rounded + k-permuted. A1/B always rounded+permuted.
// CTA 128x128, 8 warps (2m x 4n), warp tile 64x32.
// ---------------------------------------------------------------------------
#define PADK 40
#define TILE_F (128 * PADK)
#define SMEM_GEMM_BYTES (4 * TILE_F * 4)   // 2 ops x 2 bufs x 20KB

template <bool A0RAW, bool INTERMEDIATE>
__global__ __launch_bounds__(256, 2)
void sage_mma_gemm(const float* __restrict__ A0, const float* __restrict__ A1,
                   const float* __restrict__ B0t, const float* __restrict__ B1t,
                   const float* __restrict__ bias, float* __restrict__ C,
                   int K, int N) {
    extern __shared__ float sm[];
    const uint32_t sbase = smem_u32(sm);
    const int tid = threadIdx.x, lane = tid & 31, w = tid >> 5;
    const int wm = w >> 2, wn = w & 3;
    const int m0 = blockIdx.y * 128, n0 = blockIdx.x * 128;
    const int kc = K / 32;
    const int T = 2 * kc;

    float acc[4][4][4];
#pragma unroll
    for (int mi = 0; mi < 4; ++mi)
#pragma unroll
        for (int ni = 0; ni < 4; ++ni)
#pragma unroll
            for (int r = 0; r < 4; ++r) acc[mi][ni][r] = 0.f;

    const int srow = tid >> 3;
    const int sc4  = tid & 7;

    auto stage = [&](int chunk, int buf) {
        const int pair = (chunk >= kc) ? 1 : 0;
        const int k0 = (pair ? chunk - kc : chunk) * 32;
        const float* A = pair ? A1 : A0;
        const float* B = pair ? B1t : B0t;
        const uint32_t da = sbase + (uint32_t)buf * (TILE_F * 4);
        const uint32_t db = sbase + (uint32_t)(2 + buf) * (TILE_F * 4);
#pragma unroll
        for (int l = 0; l < 4; ++l) {
            int row = srow + l * 32;
            cp_async16(da + (uint32_t)(row * PADK + sc4 * 4) * 4,
                       A + (size_t)(m0 + row) * K + k0 + sc4 * 4);
        }
#pragma unroll
        for (int l = 0; l < 4; ++l) {
            int row = srow + l * 32;
            cp_async16(db + (uint32_t)(row * PADK + sc4 * 4) * 4,
                       B + (size_t)(n0 + row) * K + k0 + sc4 * 4);
        }
    };

    stage(0, 0);
    CP_COMMIT();
    int buf = 0;
    const int q = lane & 3;
    const int rr = lane >> 2;

    for (int c = 0; c < T; ++c) {
        if (c + 1 < T) {
            stage(c + 1, buf ^ 1);
            CP_COMMIT();
            CP_WAIT(1);
        } else {
            CP_WAIT(0);
        }
        __syncthreads();

        const float* As = sm + buf * TILE_F;
        const float* Bs = sm + (2 + buf) * TILE_F;
        const bool raw = A0RAW && (c < kc);
#pragma unroll
        for (int ks = 0; ks < 4; ++ks) {
            uint32_t a[4][4], b[4][2];
            if (raw) {
                // unpermuted raw fp32: scalar loads at k, k+4 with tf32 rounding
                const int cc = ks * 8 + q;
#pragma unroll
                for (int mi = 0; mi < 4; ++mi) {
                    const float* p = As + (wm * 64 + mi * 16 + rr) * PADK + cc;
                    a[mi][0] = f2tf(p[0]);
                    a[mi][1] = f2tf(p[8 * PADK]);
                    a[mi][2] = f2tf(p[4]);
                    a[mi][3] = f2tf(p[8 * PADK + 4]);
                }
            } else {
                // permuted tf32: (k, k+4) adjacent -> float2 loads
                const int cc = ks * 8 + q * 2;
#pragma unroll
                for (int mi = 0; mi < 4; ++mi) {
                    const float* p = As + (wm * 64 + mi * 16 + rr) * PADK + cc;
                    float2 lo = *(const float2*)p;
                    float2 hi = *(const float2*)(p + 8 * PADK);
                    a[mi][0] = __float_as_uint(lo.x);
                    a[mi][1] = __float_as_uint(hi.x);
                    a[mi][2] = __float_as_uint(lo.y);
                    a[mi][3] = __float_as_uint(hi.y);
                }
            }
            {
                const int cc = ks * 8 + q * 2;
#pragma unroll
                for (int ni = 0; ni < 4; ++ni) {
                    const float* p = Bs + (wn * 32 + ni * 8 + rr) * PADK + cc;
                    float2 v = *(const float2*)p;
                    b[ni][0] = __float_as_uint(v.x);
                    b[ni][1] = __float_as_uint(v.y);
                }
            }
#pragma unroll
            for (int mi = 0; mi < 4; ++mi)
#pragma unroll
                for (int ni = 0; ni < 4; ++ni)
                    mma_tf32(acc[mi][ni], a[mi][0], a[mi][1], a[mi][2], a[mi][3],
                             b[ni][0], b[ni][1]);
        }
        __syncthreads();
        buf ^= 1;
    }

    // epilogue
#pragma unroll
    for (int ni = 0; ni < 4; ++ni) {
        const int n = n0 + wn * 32 + ni * 8 + 2 * (lane & 3);
        const float bx = __ldg(bias + n), by = __ldg(bias + n + 1);
#pragma unroll
        for (int mi = 0; mi < 4; ++mi) {
            const int m = m0 + wm * 64 + mi * 16 + (lane >> 2);
            float v00 = acc[mi][ni][0] + bx, v01 = acc[mi][ni][1] + by;
            float v10 = acc[mi][ni][2] + bx, v11 = acc[mi][ni][3] + by;
            if (INTERMEDIATE) {
                v00 = cvt_tf32(fmaxf(v00, 0.f)); v01 = cvt_tf32(fmaxf(v01, 0.f));
                v10 = cvt_tf32(fmaxf(v10, 0.f)); v11 = cvt_tf32(fmaxf(v11, 0.f));
                const int g = n & ~7;
                const int p0 = g | perm8(n & 7), p1 = g | perm8((n + 1) & 7);
                C[(size_t)m * N + p0] = v00;
                C[(size_t)m * N + p1] = v01;
                C[(size_t)(m + 8) * N + p0] = v10;
                C[(size_t)(m + 8) * N + p1] = v11;
            } else {
                *(float2*)(C + (size_t)m * N + n) = make_float2(v00, v01);
                *(float2*)(C + (size_t)(m + 8) * N + n) = make_float2(v10, v11);
            }
        }
    }
}

// ---------------------------------------------------------------------------
extern "C" void kernel_launch(void* const* d_in, const int* in_sizes, int n_in,
                              void* d_out, int out_size) {
    const float* x   = (const float*)d_in[0];
    const float* Ws0 = (const float*)d_in[1];
    const float* Wn0 = (const float*)d_in[2];
    const float* b0  = (const float*)d_in[3];
    const float* Ws1 = (const float*)d_in[4];
    const float* Wn1 = (const float*)d_in[5];
    const float* b1  = (const float*)d_in[6];
    const float* Ws2 = (const float*)d_in[7];
    const float* Wn2 = (const float*)d_in[8];
    const float* b2  = (const float*)d_in[9];
    const int*   e0  = (const int*)d_in[10];
    const int*   e1  = (const int*)d_in[11];
    const int*   e2  = (const int*)d_in[12];
    float* out = (float*)d_out;

    float *neigh0, *h1, *neigh1, *h2, *neigh2;
    float *Wt0s, *Wt0n, *Wt1s, *Wt1n, *Wt2s, *Wt2n;
    cudaGetSymbolAddress((void**)&neigh0, g_neigh0);
    cudaGetSymbolAddress((void**)&h1,     g_h1);
    cudaGetSymbolAddress((void**)&neigh1, g_neigh1);
    cudaGetSymbolAddress((void**)&h2,     g_h2);
    cudaGetSymbolAddress((void**)&neigh2, g_neigh2);
    cudaGetSymbolAddress((void**)&Wt0s,   g_Wt0s);
    cudaGetSymbolAddress((void**)&Wt0n,   g_Wt0n);
    cudaGetSymbolAddress((void**)&Wt1s,   g_Wt1s);
    cudaGetSymbolAddress((void**)&Wt1n,   g_Wt1n);
    cudaGetSymbolAddress((void**)&Wt2s,   g_Wt2s);
    cudaGetSymbolAddress((void**)&Wt2n,   g_Wt2n);

    cudaFuncSetAttribute((const void*)sage_mma_gemm<true, true>,
                         cudaFuncAttributeMaxDynamicSharedMemorySize, SMEM_GEMM_BYTES);
    cudaFuncSetAttribute((const void*)sage_mma_gemm<false, true>,
                         cudaFuncAttributeMaxDynamicSharedMemorySize, SMEM_GEMM_BYTES);
    cudaFuncSetAttribute((const void*)sage_mma_gemm<false, false>,
                         cudaFuncAttributeMaxDynamicSharedMemorySize, SMEM_GEMM_BYTES);

    // #1: gather0 (raw x -> rounded+permuted neigh0)
    gather_mean_kernel<true><<<N1_SZ / 8, dim3(IN_DIM / 8, 8)>>>(x, e0, neigh0, IN_DIM / 8, N1_SZ);
    // #2: all 6 weight transposes in one launch
    transpose_all_kernel<<<1024, dim3(32, 8)>>>(Ws0, Wt0s, Wn0, Wt0n,
                                                Ws1, Wt1s, Wn1, Wt1n,
                                                Ws2, Wt2s, Wn2, Wt2n);
    // #3: Layer-0 dual GEMM (A0 = raw x, cvt in fragment path)
    sage_mma_gemm<true, true><<<dim3(H_DIM / 128, N1_SZ / 128), 256, SMEM_GEMM_BYTES>>>(
        x, neigh0, Wt0s, Wt0n, b0, h1, IN_DIM, H_DIM);
    // #4: gather1
    gather_mean_kernel<false><<<N2_SZ / 4, dim3(H_DIM / 8, 4)>>>(h1, e1, neigh1, H_DIM / 8, N2_SZ);
    // #5: Layer-1 dual GEMM
    sage_mma_gemm<false, true><<<dim3(H_DIM / 128, N2_SZ / 128), 256, SMEM_GEMM_BYTES>>>(
        h1, neigh1, Wt1s, Wt1n, b1, h2, H_DIM, H_DIM);
    // #6: gather2
    gather_mean_kernel<false><<<SEEDS_SZ / 4, dim3(H_DIM / 8, 4)>>>(h2, e2, neigh2, H_DIM / 8, SEEDS_SZ);
    // #7: Layer-2 dual GEMM (canonical output layout)
    sage_mma_gemm<false, false><<<dim3(C_DIM / 128, SEEDS_SZ / 128), 256, SMEM_GEMM_BYTES>>>(
        h2, neigh2, Wt2s, Wt2n, b2, out, H_DIM, C_DIM);
}

// round 7
// speedup vs baseline: 1.0971x; 1.0846x over previous
#include <cuda_runtime.h>
#include <cstdint>
#include <cstddef>

// ---------------- problem constants ----------------
#define FANOUT 10
#define N0_SZ 1362944
#define N1_SZ 123904
#define N2_SZ 11264
#define SEEDS_SZ 1024
#define IN_DIM 256
#define H_DIM 512
#define C_DIM 256

// ---------------- device scratch (allocation-free rule) ----------------
__device__ __align__(16) float g_xr[(size_t)N1_SZ * IN_DIM];       // rounded+perm x[:N1]
__device__ __align__(16) float g_neigh0[(size_t)N1_SZ * IN_DIM];
__device__ __align__(16) float g_h1[(size_t)N1_SZ * H_DIM];
__device__ __align__(16) float g_neigh1[(size_t)N2_SZ * H_DIM];
__device__ __align__(16) float g_h2[(size_t)N2_SZ * H_DIM];
__device__ __align__(16) float g_neigh2[(size_t)SEEDS_SZ * H_DIM];
// transposed + tf32-rounded + k-permuted weights: Wt[n][perm(k)] = tf32(W[k][n])
__device__ __align__(16) float g_Wt0s[(size_t)H_DIM * IN_DIM];
__device__ __align__(16) float g_Wt0n[(size_t)H_DIM * IN_DIM];
__device__ __align__(16) float g_Wt1s[(size_t)H_DIM * H_DIM];
__device__ __align__(16) float g_Wt1n[(size_t)H_DIM * H_DIM];
__device__ __align__(16) float g_Wt2s[(size_t)C_DIM * H_DIM];
__device__ __align__(16) float g_Wt2n[(size_t)C_DIM * H_DIM];

// ---------------- helpers (portable sm_80+ PTX) ----------------
__device__ __forceinline__ uint32_t smem_u32(const void* p) {
    uint32_t a;
    asm("{ .reg .u64 t; cvta.to.shared.u64 t, %1; cvt.u32.u64 %0, t; }" : "=r"(a) : "l"(p));
    return a;
}
__device__ __forceinline__ float cvt_tf32(float x) {
    float r; asm("cvt.rna.tf32.f32 %0, %1;" : "=f"(r) : "f"(x)); return r;
}
__device__ __forceinline__ void cp_async16(uint32_t dst, const void* src) {
    asm volatile("cp.async.cg.shared.global [%0], [%1], 16;" :: "r"(dst), "l"(src));
}
#define CP_COMMIT() asm volatile("cp.async.commit_group;" ::: "memory")
#define CP_WAIT(n)  asm volatile("cp.async.wait_group %0;" :: "n"(n) : "memory")

__device__ __forceinline__ void mma_tf32(float c[4],
                                         uint32_t a0, uint32_t a1, uint32_t a2, uint32_t a3,
                                         uint32_t b0, uint32_t b1) {
    asm volatile(
        "mma.sync.aligned.m16n8k8.row.col.f32.tf32.tf32.f32 "
        "{%0,%1,%2,%3}, {%4,%5,%6,%7}, {%8,%9}, {%0,%1,%2,%3};"
        : "+f"(c[0]), "+f"(c[1]), "+f"(c[2]), "+f"(c[3])
        : "r"(a0), "r"(a1), "r"(a2), "r"(a3), "r"(b0), "r"(b1));
}

__host__ __device__ __forceinline__ int perm8(int i) { return (i & 3) * 2 + (i >> 2); }

// ---------------------------------------------------------------------------
// Layer-0 fused gather + self-row prep:
//   neigh0[d] = perm(tf32(mean_{e} x[src[d*10+e]]))
//   xr[d]     = perm(tf32(x[d]))                (d < N1 == dst rows)
// block (32, 8): 8 dst rows per block, 32 threads cover 256 cols (8 each).
// ---------------------------------------------------------------------------
__global__ void gather0_fused_kernel(const float* __restrict__ x,
                                     const int* __restrict__ src,
                                     float* __restrict__ neigh0,
                                     float* __restrict__ xr) {
    const int d = blockIdx.x * blockDim.y + threadIdx.y;
    const int t = threadIdx.x;                  // 0..31, 8 floats each
    const int dim8 = IN_DIM / 8;                // 32
    const int* s = src + (size_t)d * FANOUT;
    const float4* x4 = (const float4*)x;

    float4 a0 = make_float4(0.f, 0.f, 0.f, 0.f);
    float4 a1 = make_float4(0.f, 0.f, 0.f, 0.f);
#pragma unroll
    for (int e = 0; e < FANOUT; ++e) {
        int r = __ldg(s + e);
        const float4* p = x4 + ((size_t)r * dim8 + t) * 2;
        float4 v0 = __ldg(p), v1 = __ldg(p + 1);
        a0.x += v0.x; a0.y += v0.y; a0.z += v0.z; a0.w += v0.w;
        a1.x += v1.x; a1.y += v1.y; a1.z += v1.z; a1.w += v1.w;
    }
    const float inv = 1.0f / FANOUT;
    a0.x = cvt_tf32(a0.x * inv); a0.y = cvt_tf32(a0.y * inv);
    a0.z = cvt_tf32(a0.z * inv); a0.w = cvt_tf32(a0.w * inv);
    a1.x = cvt_tf32(a1.x * inv); a1.y = cvt_tf32(a1.y * inv);
    a1.z = cvt_tf32(a1.z * inv); a1.w = cvt_tf32(a1.w * inv);

    float4* o = (float4*)neigh0 + ((size_t)d * dim8 + t) * 2;
    o[0] = make_float4(a0.x, a1.x, a0.y, a1.y);   // perm within 8-group
    o[1] = make_float4(a0.z, a1.z, a0.w, a1.w);

    // self row: round + permute x[d] into xr[d]
    const float4* p = x4 + ((size_t)d * dim8 + t) * 2;
    float4 v0 = __ldg(p), v1 = __ldg(p + 1);
    v0.x = cvt_tf32(v0.x); v0.y = cvt_tf32(v0.y); v0.z = cvt_tf32(v0.z); v0.w = cvt_tf32(v0.w);
    v1.x = cvt_tf32(v1.x); v1.y = cvt_tf32(v1.y); v1.z = cvt_tf32(v1.z); v1.w = cvt_tf32(v1.w);
    float4* ox = (float4*)xr + ((size_t)d * dim8 + t) * 2;
    ox[0] = make_float4(v0.x, v1.x, v0.y, v1.y);
    ox[1] = make_float4(v0.z, v1.z, v0.w, v1.w);
}

// ---------------------------------------------------------------------------
// gather-mean, layout-preserving (input already rounded+permuted)
// ---------------------------------------------------------------------------
__global__ void gather_mean_kernel(const float* __restrict__ h,
                                   const int* __restrict__ src,
                                   float* __restrict__ out, int dim8, int num_dst) {
    const int d = blockIdx.x * blockDim.y + threadIdx.y;
    if (d >= num_dst) return;
    const int t = threadIdx.x;
    const int* s = src + (size_t)d * FANOUT;
    const float4* h4 = (const float4*)h;

    float4 a0 = make_float4(0.f, 0.f, 0.f, 0.f);
    float4 a1 = make_float4(0.f, 0.f, 0.f, 0.f);
#pragma unroll
    for (int e = 0; e < FANOUT; ++e) {
        int r = __ldg(s + e);
        const float4* p = h4 + ((size_t)r * dim8 + t) * 2;
        float4 v0 = __ldg(p), v1 = __ldg(p + 1);
        a0.x += v0.x; a0.y += v0.y; a0.z += v0.z; a0.w += v0.w;
        a1.x += v1.x; a1.y += v1.y; a1.z += v1.z; a1.w += v1.w;
    }
    const float inv = 1.0f / FANOUT;
    a0.x = cvt_tf32(a0.x * inv); a0.y = cvt_tf32(a0.y * inv);
    a0.z = cvt_tf32(a0.z * inv); a0.w = cvt_tf32(a0.w * inv);
    a1.x = cvt_tf32(a1.x * inv); a1.y = cvt_tf32(a1.y * inv);
    a1.z = cvt_tf32(a1.z * inv); a1.w = cvt_tf32(a1.w * inv);

    float4* o = (float4*)out + ((size_t)d * dim8 + t) * 2;
    o[0] = a0;
    o[1] = a1;
}

// ---------------------------------------------------------------------------
// Merged weight transpose: all 6 W[K,N] -> Wt[N, perm(K)] in ONE launch.
// ---------------------------------------------------------------------------
__global__ void transpose_all_kernel(const float* W0, float* D0,
                                     const float* W1, float* D1,
                                     const float* W2, float* D2,
                                     const float* W3, float* D3,
                                     const float* W4, float* D4,
                                     const float* W5, float* D5) {
    const int b = blockIdx.x;
    const float* W; float* Wt; int K, N, t;
    if (b < 256) {
        K = IN_DIM; N = H_DIM;
        if (b < 128) { W = W0; Wt = D0; t = b; }
        else         { W = W1; Wt = D1; t = b - 128; }
    } else if (b < 768) {
        K = H_DIM; N = H_DIM;
        if (b < 512) { W = W2; Wt = D2; t = b - 256; }
        else         { W = W3; Wt = D3; t = b - 512; }
    } else {
        K = H_DIM; N = C_DIM;
        if (b < 896) { W = W4; Wt = D4; t = b - 768; }
        else         { W = W5; Wt = D5; t = b - 896; }
    }
    const int ntx = N / 32;
    const int bx = (t % ntx) * 32, by = (t / ntx) * 32;

    __shared__ float tile[32][33];
#pragma unroll
    for (int i = threadIdx.y; i < 32; i += 8)
        tile[i][threadIdx.x] = __ldg(W + (size_t)(by + i) * N + bx + threadIdx.x);
    __syncthreads();
#pragma unroll
    for (int i = threadIdx.y; i < 32; i += 8) {
        int k = by + threadIdx.x;
        int kp = (k & ~7) | perm8(k & 7);
        Wt[(size_t)(bx + i) * K + kp] = cvt_tf32(tile[threadIdx.x][i]);
    }
}

// ---------------------------------------------------------------------------
// tf32 mma.sync dual-GEMM — exact R3 config (BK=32, PADK=40, 2-stage, BN=128).
// All operands tf32-rounded + k-permuted. 8 warps (2m x 4n), warp tile 64x32.
// ---------------------------------------------------------------------------
#define PADK 40
#define TILE_F (128 * PADK)
#define SMEM_GEMM_BYTES (4 * TILE_F * 4)

template <bool INTERMEDIATE>
__global__ __launch_bounds__(256, 2)
void sage_mma_gemm(const float* __restrict__ A0, const float* __restrict__ A1,
                   const float* __restrict__ B0t, const float* __restrict__ B1t,
                   const float* __restrict__ bias, float* __restrict__ C,
                   int K, int N) {
    extern __shared__ float sm[];
    const uint32_t sbase = smem_u32(sm);
    const int tid = threadIdx.x, lane = tid & 31, w = tid >> 5;
    const int wm = w >> 2, wn = w & 3;
    const int m0 = blockIdx.y * 128, n0 = blockIdx.x * 128;
    const int kc = K / 32;
    const int T = 2 * kc;

    float acc[4][4][4];
#pragma unroll
    for (int mi = 0; mi < 4; ++mi)
#pragma unroll
        for (int ni = 0; ni < 4; ++ni)
#pragma unroll
            for (int r = 0; r < 4; ++r) acc[mi][ni][r] = 0.f;

    const int srow = tid >> 3;
    const int sc4  = tid & 7;

    auto stage = [&](int chunk, int buf) {
        const int pair = (chunk >= kc) ? 1 : 0;
        const int k0 = (pair ? chunk - kc : chunk) * 32;
        const float* A = pair ? A1 : A0;
        const float* B = pair ? B1t : B0t;
        const uint32_t da = sbase + (uint32_t)buf * (TILE_F * 4);
        const uint32_t db = sbase + (uint32_t)(2 + buf) * (TILE_F * 4);
#pragma unroll
        for (int l = 0; l < 4; ++l) {
            int row = srow + l * 32;
            cp_async16(da + (uint32_t)(row * PADK + sc4 * 4) * 4,
                       A + (size_t)(m0 + row) * K + k0 + sc4 * 4);
        }
#pragma unroll
        for (int l = 0; l < 4; ++l) {
            int row = srow + l * 32;
            cp_async16(db + (uint32_t)(row * PADK + sc4 * 4) * 4,
                       B + (size_t)(n0 + row) * K + k0 + sc4 * 4);
        }
    };

    stage(0, 0);
    CP_COMMIT();
    int buf = 0;
    const int q2 = (lane & 3) * 2;
    const int rr = lane >> 2;

    for (int c = 0; c < T; ++c) {
        if (c + 1 < T) {
            stage(c + 1, buf ^ 1);
            CP_COMMIT();
            CP_WAIT(1);
        } else {
            CP_WAIT(0);
        }
        __syncthreads();

        const float* As = sm + buf * TILE_F;
        const float* Bs = sm + (2 + buf) * TILE_F;
#pragma unroll
        for (int ks = 0; ks < 4; ++ks) {
            uint32_t a[4][4], b[4][2];
            const int cc = ks * 8 + q2;
#pragma unroll
            for (int mi = 0; mi < 4; ++mi) {
                const float* p = As + (wm * 64 + mi * 16 + rr) * PADK + cc;
                float2 lo = *(const float2*)p;
                float2 hi = *(const float2*)(p + 8 * PADK);
                a[mi][0] = __float_as_uint(lo.x);
                a[mi][1] = __float_as_uint(hi.x);
                a[mi][2] = __float_as_uint(lo.y);
                a[mi][3] = __float_as_uint(hi.y);
            }
#pragma unroll
            for (int ni = 0; ni < 4; ++ni) {
                const float* p = Bs + (wn * 32 + ni * 8 + rr) * PADK + cc;
                float2 v = *(const float2*)p;
                b[ni][0] = __float_as_uint(v.x);
                b[ni][1] = __float_as_uint(v.y);
            }
#pragma unroll
            for (int mi = 0; mi < 4; ++mi)
#pragma unroll
                for (int ni = 0; ni < 4; ++ni)
                    mma_tf32(acc[mi][ni], a[mi][0], a[mi][1], a[mi][2], a[mi][3],
                             b[ni][0], b[ni][1]);
        }
        __syncthreads();
        buf ^= 1;
    }

    // epilogue
#pragma unroll
    for (int ni = 0; ni < 4; ++ni) {
        const int n = n0 + wn * 32 + ni * 8 + 2 * (lane & 3);
        const float bx = __ldg(bias + n), by = __ldg(bias + n + 1);
#pragma unroll
        for (int mi = 0; mi < 4; ++mi) {
            const int m = m0 + wm * 64 + mi * 16 + (lane >> 2);
            float v00 = acc[mi][ni][0] + bx, v01 = acc[mi][ni][1] + by;
            float v10 = acc[mi][ni][2] + bx, v11 = acc[mi][ni][3] + by;
            if (INTERMEDIATE) {
                v00 = cvt_tf32(fmaxf(v00, 0.f)); v01 = cvt_tf32(fmaxf(v01, 0.f));
                v10 = cvt_tf32(fmaxf(v10, 0.f)); v11 = cvt_tf32(fmaxf(v11, 0.f));
                const int g = n & ~7;
                const int p0 = g | perm8(n & 7), p1 = g | perm8((n + 1) & 7);
                C[(size_t)m * N + p0] = v00;
                C[(size_t)m * N + p1] = v01;
                C[(size_t)(m + 8) * N + p0] = v10;
                C[(size_t)(m + 8) * N + p1] = v11;
            } else {
                *(float2*)(C + (size_t)m * N + n) = make_float2(v00, v01);
                *(float2*)(C + (size_t)(m + 8) * N + n) = make_float2(v10, v11);
            }
        }
    }
}

// ---------------------------------------------------------------------------
extern "C" void kernel_launch(void* const* d_in, const int* in_sizes, int n_in,
                              void* d_out, int out_size) {
    const float* x   = (const float*)d_in[0];
    const float* Ws0 = (const float*)d_in[1];
    const float* Wn0 = (const float*)d_in[2];
    const float* b0  = (const float*)d_in[3];
    const float* Ws1 = (const float*)d_in[4];
    const float* Wn1 = (const float*)d_in[5];
    const float* b1  = (const float*)d_in[6];
    const float* Ws2 = (const float*)d_in[7];
    const float* Wn2 = (const float*)d_in[8];
    const float* b2  = (const float*)d_in[9];
    const int*   e0  = (const int*)d_in[10];
    const int*   e1  = (const int*)d_in[11];
    const int*   e2  = (const int*)d_in[12];
    float* out = (float*)d_out;

    float *xr, *neigh0, *h1, *neigh1, *h2, *neigh2;
    float *Wt0s, *Wt0n, *Wt1s, *Wt1n, *Wt2s, *Wt2n;
    cudaGetSymbolAddress((void**)&xr,     g_xr);
    cudaGetSymbolAddress((void**)&neigh0, g_neigh0);
    cudaGetSymbolAddress((void**)&h1,     g_h1);
    cudaGetSymbolAddress((void**)&neigh1, g_neigh1);
    cudaGetSymbolAddress((void**)&h2,     g_h2);
    cudaGetSymbolAddress((void**)&neigh2, g_neigh2);
    cudaGetSymbolAddress((void**)&Wt0s,   g_Wt0s);
    cudaGetSymbolAddress((void**)&Wt0n,   g_Wt0n);
    cudaGetSymbolAddress((void**)&Wt1s,   g_Wt1s);
    cudaGetSymbolAddress((void**)&Wt1n,   g_Wt1n);
    cudaGetSymbolAddress((void**)&Wt2s,   g_Wt2s);
    cudaGetSymbolAddress((void**)&Wt2n,   g_Wt2n);

    cudaFuncSetAttribute((const void*)sage_mma_gemm<true>,
                         cudaFuncAttributeMaxDynamicSharedMemorySize, SMEM_GEMM_BYTES);
    cudaFuncSetAttribute((const void*)sage_mma_gemm<false>,
                         cudaFuncAttributeMaxDynamicSharedMemorySize, SMEM_GEMM_BYTES);

    // #1: fused gather0 + xr prep
    gather0_fused_kernel<<<N1_SZ / 8, dim3(32, 8)>>>(x, e0, neigh0, xr);
    // #2: all 6 weight transposes in one launch
    transpose_all_kernel<<<1024, dim3(32, 8)>>>(Ws0, Wt0s, Wn0, Wt0n,
                                                Ws1, Wt1s, Wn1, Wt1n,
                                                Ws2, Wt2s, Wn2, Wt2n);
    // #3: Layer-0 dual GEMM
    sage_mma_gemm<true><<<dim3(H_DIM / 128, N1_SZ / 128), 256, SMEM_GEMM_BYTES>>>(
        xr, neigh0, Wt0s, Wt0n, b0, h1, IN_DIM, H_DIM);
    // #4: gather1
    gather_mean_kernel<<<N2_SZ / 4, dim3(H_DIM / 8, 4)>>>(h1, e1, neigh1, H_DIM / 8, N2_SZ);
    // #5: Layer-1 dual GEMM
    sage_mma_gemm<true><<<dim3(H_DIM / 128, N2_SZ / 128), 256, SMEM_GEMM_BYTES>>>(
        h1, neigh1, Wt1s, Wt1n, b1, h2, H_DIM, H_DIM);
    // #6: gather2
    gather_mean_kernel<<<SEEDS_SZ / 4, dim3(H_DIM / 8, 4)>>>(h2, e2, neigh2, H_DIM / 8, SEEDS_SZ);
    // #7: Layer-2 dual GEMM (canonical output layout)
    sage_mma_gemm<false><<<dim3(C_DIM / 128, SEEDS_SZ / 128), 256, SMEM_GEMM_BYTES>>>(
        h2, neigh2, Wt2s, Wt2n, b2, out, H_DIM, C_DIM);
}

// round 8
// speedup vs baseline: 1.2412x; 1.1313x over previous
#include <cuda_runtime.h>
#include <cstdint>
#include <cstddef>

// ---------------- problem constants ----------------
#define FANOUT 10
#define N0_SZ 1362944
#define N1_SZ 123904
#define N2_SZ 11264
#define SEEDS_SZ 1024
#define IN_DIM 256
#define H_DIM 512
#define C_DIM 256

#define NUNITS (N1_SZ / 128)        // 968 M-tiles in layer 0
#define GATHER_CTAS 96

// ---------------- device scratch (allocation-free rule) ----------------
__device__ __align__(16) float g_xr[(size_t)N1_SZ * IN_DIM];
__device__ __align__(16) float g_neigh0[(size_t)N1_SZ * IN_DIM];
__device__ __align__(16) float g_h1[(size_t)N1_SZ * H_DIM];
__device__ __align__(16) float g_neigh1[(size_t)N2_SZ * H_DIM];
__device__ __align__(16) float g_h2[(size_t)N2_SZ * H_DIM];
__device__ __align__(16) float g_neigh2[(size_t)SEEDS_SZ * H_DIM];
__device__ __align__(16) float g_Wt0s[(size_t)H_DIM * IN_DIM];
__device__ __align__(16) float g_Wt0n[(size_t)H_DIM * IN_DIM];
__device__ __align__(16) float g_Wt1s[(size_t)H_DIM * H_DIM];
__device__ __align__(16) float g_Wt1n[(size_t)H_DIM * H_DIM];
__device__ __align__(16) float g_Wt2s[(size_t)C_DIM * H_DIM];
__device__ __align__(16) float g_Wt2n[(size_t)C_DIM * H_DIM];
__device__ volatile unsigned g_ready[NUNITS];   // per-M-tile ready flags

// ---------------- helpers (portable sm_80+ PTX) ----------------
__device__ __forceinline__ uint32_t smem_u32(const void* p) {
    uint32_t a;
    asm("{ .reg .u64 t; cvta.to.shared.u64 t, %1; cvt.u32.u64 %0, t; }" : "=r"(a) : "l"(p));
    return a;
}
__device__ __forceinline__ float cvt_tf32(float x) {
    float r; asm("cvt.rna.tf32.f32 %0, %1;" : "=f"(r) : "f"(x)); return r;
}
__device__ __forceinline__ void cp_async16(uint32_t dst, const void* src) {
    asm volatile("cp.async.cg.shared.global [%0], [%1], 16;" :: "r"(dst), "l"(src));
}
#define CP_COMMIT() asm volatile("cp.async.commit_group;" ::: "memory")
#define CP_WAIT(n)  asm volatile("cp.async.wait_group %0;" :: "n"(n) : "memory")

__device__ __forceinline__ void mma_tf32(float c[4],
                                         uint32_t a0, uint32_t a1, uint32_t a2, uint32_t a3,
                                         uint32_t b0, uint32_t b1) {
    asm volatile(
        "mma.sync.aligned.m16n8k8.row.col.f32.tf32.tf32.f32 "
        "{%0,%1,%2,%3}, {%4,%5,%6,%7}, {%8,%9}, {%0,%1,%2,%3};"
        : "+f"(c[0]), "+f"(c[1]), "+f"(c[2]), "+f"(c[3])
        : "r"(a0), "r"(a1), "r"(a2), "r"(a3), "r"(b0), "r"(b1));
}

__host__ __device__ __forceinline__ int perm8(int i) { return (i & 3) * 2 + (i >> 2); }

#define PADK 40
#define TILE_F (128 * PADK)
#define SMEM_GEMM_BYTES (4 * TILE_F * 4)

// ---------------------------------------------------------------------------
// Layer-0 fused producer/consumer kernel.
//  Blocks [0, GATHER_CTAS): gather role — produce neigh0 + xr per 128-row unit,
//    then publish the unit's ready flag.
//  Blocks [GATHER_CTAS, GATHER_CTAS+3872): GEMM role — exact R3/R7 dual-GEMM
//    tile; spins on its M-tile flag before staging. gbid = 4*m + n keeps the 4
//    same-m CTAs adjacent (L2 reuse of A tiles).
// ---------------------------------------------------------------------------
__global__ __launch_bounds__(256, 2)
void layer0_fused_kernel(const float* __restrict__ x, const int* __restrict__ e0,
                         float* __restrict__ neigh0, float* __restrict__ xr,
                         const float* __restrict__ B0t, const float* __restrict__ B1t,
                         const float* __restrict__ bias, float* __restrict__ C) {
    extern __shared__ float sm[];
    const int tid = threadIdx.x;

    if (blockIdx.x < GATHER_CTAS) {
        // ---------------- gather producer ----------------
        const int t = tid & 31;          // 32 threads cover 256 cols (8 each)
        const int ry = tid >> 5;         // 8 rows per pass
        const int dim8 = IN_DIM / 8;     // 32
        const float4* x4 = (const float4*)x;

        for (int u = blockIdx.x; u < NUNITS; u += GATHER_CTAS) {
            const int dbase = u * 128;
#pragma unroll 1
            for (int pass = 0; pass < 16; ++pass) {
                const int d = dbase + pass * 8 + ry;
                const int* s = e0 + (size_t)d * FANOUT;

                float4 a0 = make_float4(0.f, 0.f, 0.f, 0.f);
                float4 a1 = make_float4(0.f, 0.f, 0.f, 0.f);
#pragma unroll
                for (int e = 0; e < FANOUT; ++e) {
                    int r = __ldg(s + e);
                    const float4* p = x4 + ((size_t)r * dim8 + t) * 2;
                    float4 v0 = __ldg(p), v1 = __ldg(p + 1);
                    a0.x += v0.x; a0.y += v0.y; a0.z += v0.z; a0.w += v0.w;
                    a1.x += v1.x; a1.y += v1.y; a1.z += v1.z; a1.w += v1.w;
                }
                const float inv = 1.0f / FANOUT;
                a0.x = cvt_tf32(a0.x * inv); a0.y = cvt_tf32(a0.y * inv);
                a0.z = cvt_tf32(a0.z * inv); a0.w = cvt_tf32(a0.w * inv);
                a1.x = cvt_tf32(a1.x * inv); a1.y = cvt_tf32(a1.y * inv);
                a1.z = cvt_tf32(a1.z * inv); a1.w = cvt_tf32(a1.w * inv);

                float4* o = (float4*)neigh0 + ((size_t)d * dim8 + t) * 2;
                o[0] = make_float4(a0.x, a1.x, a0.y, a1.y);
                o[1] = make_float4(a0.z, a1.z, a0.w, a1.w);

                const float4* p = x4 + ((size_t)d * dim8 + t) * 2;
                float4 v0 = __ldg(p), v1 = __ldg(p + 1);
                v0.x = cvt_tf32(v0.x); v0.y = cvt_tf32(v0.y);
                v0.z = cvt_tf32(v0.z); v0.w = cvt_tf32(v0.w);
                v1.x = cvt_tf32(v1.x); v1.y = cvt_tf32(v1.y);
                v1.z = cvt_tf32(v1.z); v1.w = cvt_tf32(v1.w);
                float4* ox = (float4*)xr + ((size_t)d * dim8 + t) * 2;
                ox[0] = make_float4(v0.x, v1.x, v0.y, v1.y);
                ox[1] = make_float4(v0.z, v1.z, v0.w, v1.w);
            }
            __threadfence();
            __syncthreads();
            if (tid == 0) g_ready[u] = 1;
        }
        return;
    }

    // ---------------- GEMM consumer (layer 0: K=256, N=512) ----------------
    const int gbid = (int)blockIdx.x - GATHER_CTAS;
    const int n0 = (gbid & 3) * 128;
    const int mu = gbid >> 2;            // M-tile / ready-flag index
    const int m0 = mu * 128;

    if (tid == 0) {
        while (g_ready[mu] == 0) { __nanosleep(128); }
    }
    __syncthreads();

    const uint32_t sbase = smem_u32(sm);
    const int lane = tid & 31, w = tid >> 5;
    const int wm = w >> 2, wn = w & 3;
    const int K = IN_DIM, N = H_DIM;
    const int kc = K / 32;               // 8
    const int T = 2 * kc;                // 16

    float acc[4][4][4];
#pragma unroll
    for (int mi = 0; mi < 4; ++mi)
#pragma unroll
        for (int ni = 0; ni < 4; ++ni)
#pragma unroll
            for (int r = 0; r < 4; ++r) acc[mi][ni][r] = 0.f;

    const int srow = tid >> 3;
    const int sc4  = tid & 7;

    auto stage = [&](int chunk, int buf) {
        const int pair = (chunk >= kc) ? 1 : 0;
        const int k0 = (pair ? chunk - kc : chunk) * 32;
        const float* A = pair ? neigh0 : xr;
        const float* B = pair ? B1t : B0t;
        const uint32_t da = sbase + (uint32_t)buf * (TILE_F * 4);
        const uint32_t db = sbase + (uint32_t)(2 + buf) * (TILE_F * 4);
#pragma unroll
        for (int l = 0; l < 4; ++l) {
            int row = srow + l * 32;
            cp_async16(da + (uint32_t)(row * PADK + sc4 * 4) * 4,
                       A + (size_t)(m0 + row) * K + k0 + sc4 * 4);
        }
#pragma unroll
        for (int l = 0; l < 4; ++l) {
            int row = srow + l * 32;
            cp_async16(db + (uint32_t)(row * PADK + sc4 * 4) * 4,
                       B + (size_t)(n0 + row) * K + k0 + sc4 * 4);
        }
    };

    stage(0, 0);
    CP_COMMIT();
    int buf = 0;
    const int q2 = (lane & 3) * 2;
    const int rr = lane >> 2;

    for (int c = 0; c < T; ++c) {
        if (c + 1 < T) {
            stage(c + 1, buf ^ 1);
            CP_COMMIT();
            CP_WAIT(1);
        } else {
            CP_WAIT(0);
        }
        __syncthreads();

        const float* As = sm + buf * TILE_F;
        const float* Bs = sm + (2 + buf) * TILE_F;
#pragma unroll
        for (int ks = 0; ks < 4; ++ks) {
            uint32_t a[4][4], b[4][2];
            const int cc = ks * 8 + q2;
#pragma unroll
            for (int mi = 0; mi < 4; ++mi) {
                const float* p = As + (wm * 64 + mi * 16 + rr) * PADK + cc;
                float2 lo = *(const float2*)p;
                float2 hi = *(const float2*)(p + 8 * PADK);
                a[mi][0] = __float_as_uint(lo.x);
                a[mi][1] = __float_as_uint(hi.x);
                a[mi][2] = __float_as_uint(lo.y);
                a[mi][3] = __float_as_uint(hi.y);
            }
#pragma unroll
            for (int ni = 0; ni < 4; ++ni) {
                const float* p = Bs + (wn * 32 + ni * 8 + rr) * PADK + cc;
                float2 v = *(const float2*)p;
                b[ni][0] = __float_as_uint(v.x);
                b[ni][1] = __float_as_uint(v.y);
            }
#pragma unroll
            for (int mi = 0; mi < 4; ++mi)
#pragma unroll
                for (int ni = 0; ni < 4; ++ni)
                    mma_tf32(acc[mi][ni], a[mi][0], a[mi][1], a[mi][2], a[mi][3],
                             b[ni][0], b[ni][1]);
        }
        __syncthreads();
        buf ^= 1;
    }

    // epilogue: bias + ReLU + tf32 round + permuted store (feeds layer 1)
#pragma unroll
    for (int ni = 0; ni < 4; ++ni) {
        const int n = n0 + wn * 32 + ni * 8 + 2 * (lane & 3);
        const float bx = __ldg(bias + n), by = __ldg(bias + n + 1);
#pragma unroll
        for (int mi = 0; mi < 4; ++mi) {
            const int m = m0 + wm * 64 + mi * 16 + (lane >> 2);
            float v00 = cvt_tf32(fmaxf(acc[mi][ni][0] + bx, 0.f));
            float v01 = cvt_tf32(fmaxf(acc[mi][ni][1] + by, 0.f));
            float v10 = cvt_tf32(fmaxf(acc[mi][ni][2] + bx, 0.f));
            float v11 = cvt_tf32(fmaxf(acc[mi][ni][3] + by, 0.f));
            const int g = n & ~7;
            const int p0 = g | perm8(n & 7), p1 = g | perm8((n + 1) & 7);
            C[(size_t)m * N + p0] = v00;
            C[(size_t)m * N + p1] = v01;
            C[(size_t)(m + 8) * N + p0] = v10;
            C[(size_t)(m + 8) * N + p1] = v11;
        }
    }
}

// ---------------------------------------------------------------------------
// gather-mean, layout-preserving (input already rounded+permuted)
// ---------------------------------------------------------------------------
__global__ void gather_mean_kernel(const float* __restrict__ h,
                                   const int* __restrict__ src,
                                   float* __restrict__ out, int dim8, int num_dst) {
    const int d = blockIdx.x * blockDim.y + threadIdx.y;
    if (d >= num_dst) return;
    const int t = threadIdx.x;
    const int* s = src + (size_t)d * FANOUT;
    const float4* h4 = (const float4*)h;

    float4 a0 = make_float4(0.f, 0.f, 0.f, 0.f);
    float4 a1 = make_float4(0.f, 0.f, 0.f, 0.f);
#pragma unroll
    for (int e = 0; e < FANOUT; ++e) {
        int r = __ldg(s + e);
        const float4* p = h4 + ((size_t)r * dim8 + t) * 2;
        float4 v0 = __ldg(p), v1 = __ldg(p + 1);
        a0.x += v0.x; a0.y += v0.y; a0.z += v0.z; a0.w += v0.w;
        a1.x += v1.x; a1.y += v1.y; a1.z += v1.z; a1.w += v1.w;
    }
    const float inv = 1.0f / FANOUT;
    a0.x = cvt_tf32(a0.x * inv); a0.y = cvt_tf32(a0.y * inv);
    a0.z = cvt_tf32(a0.z * inv); a0.w = cvt_tf32(a0.w * inv);
    a1.x = cvt_tf32(a1.x * inv); a1.y = cvt_tf32(a1.y * inv);
    a1.z = cvt_tf32(a1.z * inv); a1.w = cvt_tf32(a1.w * inv);

    float4* o = (float4*)out + ((size_t)d * dim8 + t) * 2;
    o[0] = a0;
    o[1] = a1;
}

// ---------------------------------------------------------------------------
// Merged weight transpose (6 jobs) + ready-flag clear, ONE launch.
// ---------------------------------------------------------------------------
__global__ void transpose_all_kernel(const float* W0, float* D0,
                                     const float* W1, float* D1,
                                     const float* W2, float* D2,
                                     const float* W3, float* D3,
                                     const float* W4, float* D4,
                                     const float* W5, float* D5) {
    const int b = blockIdx.x;
    const int tid = threadIdx.y * 32 + threadIdx.x;
    if (b == 0) {   // clear layer-0 ready flags (fresh every graph replay)
        for (int i = tid; i < NUNITS; i += 256) g_ready[i] = 0;
    }
    const float* W; float* Wt; int K, N, t;
    if (b < 256) {
        K = IN_DIM; N = H_DIM;
        if (b < 128) { W = W0; Wt = D0; t = b; }
        else         { W = W1; Wt = D1; t = b - 128; }
    } else if (b < 768) {
        K = H_DIM; N = H_DIM;
        if (b < 512) { W = W2; Wt = D2; t = b - 256; }
        else         { W = W3; Wt = D3; t = b - 512; }
    } else {
        K = H_DIM; N = C_DIM;
        if (b < 896) { W = W4; Wt = D4; t = b - 768; }
        else         { W = W5; Wt = D5; t = b - 896; }
    }
    const int ntx = N / 32;
    const int bx = (t % ntx) * 32, by = (t / ntx) * 32;

    __shared__ float tile[32][33];
#pragma unroll
    for (int i = threadIdx.y; i < 32; i += 8)
        tile[i][threadIdx.x] = __ldg(W + (size_t)(by + i) * N + bx + threadIdx.x);
    __syncthreads();
#pragma unroll
    for (int i = threadIdx.y; i < 32; i += 8) {
        int k = by + threadIdx.x;
        int kp = (k & ~7) | perm8(k & 7);
        Wt[(size_t)(bx + i) * K + kp] = cvt_tf32(tile[threadIdx.x][i]);
    }
}

// ---------------------------------------------------------------------------
// tf32 mma.sync dual-GEMM (R3 config) for layers 1 and 2.
// ---------------------------------------------------------------------------
template <bool INTERMEDIATE>
__global__ __launch_bounds__(256, 2)
void sage_mma_gemm(const float* __restrict__ A0, const float* __restrict__ A1,
                   const float* __restrict__ B0t, const float* __restrict__ B1t,
                   const float* __restrict__ bias, float* __restrict__ C,
                   int K, int N) {
    extern __shared__ float sm[];
    const uint32_t sbase = smem_u32(sm);
    const int tid = threadIdx.x, lane = tid & 31, w = tid >> 5;
    const int wm = w >> 2, wn = w & 3;
    const int m0 = blockIdx.y * 128, n0 = blockIdx.x * 128;
    const int kc = K / 32;
    const int T = 2 * kc;

    float acc[4][4][4];
#pragma unroll
    for (int mi = 0; mi < 4; ++mi)
#pragma unroll
        for (int ni = 0; ni < 4; ++ni)
#pragma unroll
            for (int r = 0; r < 4; ++r) acc[mi][ni][r] = 0.f;

    const int srow = tid >> 3;
    const int sc4  = tid & 7;

    auto stage = [&](int chunk, int buf) {
        const int pair = (chunk >= kc) ? 1 : 0;
        const int k0 = (pair ? chunk - kc : chunk) * 32;
        const float* A = pair ? A1 : A0;
        const float* B = pair ? B1t : B0t;
        const uint32_t da = sbase + (uint32_t)buf * (TILE_F * 4);
        const uint32_t db = sbase + (uint32_t)(2 + buf) * (TILE_F * 4);
#pragma unroll
        for (int l = 0; l < 4; ++l) {
            int row = srow + l * 32;
            cp_async16(da + (uint32_t)(row * PADK + sc4 * 4) * 4,
                       A + (size_t)(m0 + row) * K + k0 + sc4 * 4);
        }
#pragma unroll
        for (int l = 0; l < 4; ++l) {
            int row = srow + l * 32;
            cp_async16(db + (uint32_t)(row * PADK + sc4 * 4) * 4,
                       B + (size_t)(n0 + row) * K + k0 + sc4 * 4);
        }
    };

    stage(0, 0);
    CP_COMMIT();
    int buf = 0;
    const int q2 = (lane & 3) * 2;
    const int rr = lane >> 2;

    for (int c = 0; c < T; ++c) {
        if (c + 1 < T) {
            stage(c + 1, buf ^ 1);
            CP_COMMIT();
            CP_WAIT(1);
        } else {
            CP_WAIT(0);
        }
        __syncthreads();

        const float* As = sm + buf * TILE_F;
        const float* Bs = sm + (2 + buf) * TILE_F;
#pragma unroll
        for (int ks = 0; ks < 4; ++ks) {
            uint32_t a[4][4], b[4][2];
            const int cc = ks * 8 + q2;
#pragma unroll
            for (int mi = 0; mi < 4; ++mi) {
                const float* p = As + (wm * 64 + mi * 16 + rr) * PADK + cc;
                float2 lo = *(const float2*)p;
                float2 hi = *(const float2*)(p + 8 * PADK);
                a[mi][0] = __float_as_uint(lo.x);
                a[mi][1] = __float_as_uint(hi.x);
                a[mi][2] = __float_as_uint(lo.y);
                a[mi][3] = __float_as_uint(hi.y);
            }
#pragma unroll
            for (int ni = 0; ni < 4; ++ni) {
                const float* p = Bs + (wn * 32 + ni * 8 + rr) * PADK + cc;
                float2 v = *(const float2*)p;
                b[ni][0] = __float_as_uint(v.x);
                b[ni][1] = __float_as_uint(v.y);
            }
#pragma unroll
            for (int mi = 0; mi < 4; ++mi)
#pragma unroll
                for (int ni = 0; ni < 4; ++ni)
                    mma_tf32(acc[mi][ni], a[mi][0], a[mi][1], a[mi][2], a[mi][3],
                             b[ni][0], b[ni][1]);
        }
        __syncthreads();
        buf ^= 1;
    }

#pragma unroll
    for (int ni = 0; ni < 4; ++ni) {
        const int n = n0 + wn * 32 + ni * 8 + 2 * (lane & 3);
        const float bx = __ldg(bias + n), by = __ldg(bias + n + 1);
#pragma unroll
        for (int mi = 0; mi < 4; ++mi) {
            const int m = m0 + wm * 64 + mi * 16 + (lane >> 2);
            float v00 = acc[mi][ni][0] + bx, v01 = acc[mi][ni][1] + by;
            float v10 = acc[mi][ni][2] + bx, v11 = acc[mi][ni][3] + by;
            if (INTERMEDIATE) {
                v00 = cvt_tf32(fmaxf(v00, 0.f)); v01 = cvt_tf32(fmaxf(v01, 0.f));
                v10 = cvt_tf32(fmaxf(v10, 0.f)); v11 = cvt_tf32(fmaxf(v11, 0.f));
                const int g = n & ~7;
                const int p0 = g | perm8(n & 7), p1 = g | perm8((n + 1) & 7);
                C[(size_t)m * N + p0] = v00;
                C[(size_t)m * N + p1] = v01;
                C[(size_t)(m + 8) * N + p0] = v10;
                C[(size_t)(m + 8) * N + p1] = v11;
            } else {
                *(float2*)(C + (size_t)m * N + n) = make_float2(v00, v01);
                *(float2*)(C + (size_t)(m + 8) * N + n) = make_float2(v10, v11);
            }
        }
    }
}

// ---------------------------------------------------------------------------
extern "C" void kernel_launch(void* const* d_in, const int* in_sizes, int n_in,
                              void* d_out, int out_size) {
    const float* x   = (const float*)d_in[0];
    const float* Ws0 = (const float*)d_in[1];
    const float* Wn0 = (const float*)d_in[2];
    const float* b0  = (const float*)d_in[3];
    const float* Ws1 = (const float*)d_in[4];
    const float* Wn1 = (const float*)d_in[5];
    const float* b1  = (const float*)d_in[6];
    const float* Ws2 = (const float*)d_in[7];
    const float* Wn2 = (const float*)d_in[8];
    const float* b2  = (const float*)d_in[9];
    const int*   e0  = (const int*)d_in[10];
    const int*   e1  = (const int*)d_in[11];
    const int*   e2  = (const int*)d_in[12];
    float* out = (float*)d_out;

    float *xr, *neigh0, *h1, *neigh1, *h2, *neigh2;
    float *Wt0s, *Wt0n, *Wt1s, *Wt1n, *Wt2s, *Wt2n;
    cudaGetSymbolAddress((void**)&xr,     g_xr);
    cudaGetSymbolAddress((void**)&neigh0, g_neigh0);
    cudaGetSymbolAddress((void**)&h1,     g_h1);
    cudaGetSymbolAddress((void**)&neigh1, g_neigh1);
    cudaGetSymbolAddress((void**)&h2,     g_h2);
    cudaGetSymbolAddress((void**)&neigh2, g_neigh2);
    cudaGetSymbolAddress((void**)&Wt0s,   g_Wt0s);
    cudaGetSymbolAddress((void**)&Wt0n,   g_Wt0n);
    cudaGetSymbolAddress((void**)&Wt1s,   g_Wt1s);
    cudaGetSymbolAddress((void**)&Wt1n,   g_Wt1n);
    cudaGetSymbolAddress((void**)&Wt2s,   g_Wt2s);
    cudaGetSymbolAddress((void**)&Wt2n,   g_Wt2n);

    cudaFuncSetAttribute((const void*)layer0_fused_kernel,
                         cudaFuncAttributeMaxDynamicSharedMemorySize, SMEM_GEMM_BYTES);
    cudaFuncSetAttribute((const void*)sage_mma_gemm<true>,
                         cudaFuncAttributeMaxDynamicSharedMemorySize, SMEM_GEMM_BYTES);
    cudaFuncSetAttribute((const void*)sage_mma_gemm<false>,
                         cudaFuncAttributeMaxDynamicSharedMemorySize, SMEM_GEMM_BYTES);

    // #1: transposes + flag clear (must precede layer0)
    transpose_all_kernel<<<1024, dim3(32, 8)>>>(Ws0, Wt0s, Wn0, Wt0n,
                                                Ws1, Wt1s, Wn1, Wt1n,
                                                Ws2, Wt2s, Wn2, Wt2n);
    // #2: fused layer 0 (gather producers + GEMM consumers, overlapped)
    layer0_fused_kernel<<<GATHER_CTAS + 4 * NUNITS, 256, SMEM_GEMM_BYTES>>>(
        x, e0, neigh0, xr, Wt0s, Wt0n, b0, h1);
    // #3: gather1
    gather_mean_kernel<<<N2_SZ / 4, dim3(H_DIM / 8, 4)>>>(h1, e1, neigh1, H_DIM / 8, N2_SZ);
    // #4: Layer-1 dual GEMM
    sage_mma_gemm<true><<<dim3(H_DIM / 128, N2_SZ / 128), 256, SMEM_GEMM_BYTES>>>(
        h1, neigh1, Wt1s, Wt1n, b1, h2, H_DIM, H_DIM);
    // #5: gather2
    gather_mean_kernel<<<SEEDS_SZ / 4, dim3(H_DIM / 8, 4)>>>(h2, e2, neigh2, H_DIM / 8, SEEDS_SZ);
    // #6: Layer-2 dual GEMM (canonical output layout)
    sage_mma_gemm<false><<<dim3(C_DIM / 128, SEEDS_SZ / 128), 256, SMEM_GEMM_BYTES>>>(
        h2, neigh2, Wt2s, Wt2n, b2, out, H_DIM, C_DIM);
}